// round 3
// baseline (speedup 1.0000x reference)
#include <cuda_runtime.h>
#include <cuda_fp16.h>

#define DIM 160
#define N_VOX (DIM * DIM * DIM)

// fp32 carried field (ping-pong) — used for own-voxel read (coordinates + additive term)
__device__ float4 g_f32A[N_VOX];
__device__ float4 g_f32B[N_VOX];
// fp16x4 mirror (8B/voxel) — gather source only. 16B-aligned so an even-x pair
// of voxels can be fetched with a single LDG.128.
__device__ __align__(16) uint2 g_h16A[N_VOX];
__device__ __align__(16) uint2 g_h16B[N_VOX];

__device__ __forceinline__ uint2 pack_h16(float x, float y, float z)
{
    __half2 hxy = __floats2half2_rn(x, y);
    __half2 hz  = __floats2half2_rn(z, 0.0f);
    uint2 r;
    r.x = *reinterpret_cast<unsigned int*>(&hxy);
    r.y = *reinterpret_cast<unsigned int*>(&hz);
    return r;
}

// Repack + prescale: vel (packed 12B voxels) -> fp32 + fp16 buffers, scaled 2^-n.
__global__ void __launch_bounds__(256)
repack_kernel(const float* __restrict__ vel,
              float4* __restrict__ d32, uint2* __restrict__ d16, float s)
{
    int idx = blockIdx.x * blockDim.x + threadIdx.x;
    if (idx >= N_VOX) return;
    int b = idx * 3;
    float x = vel[b] * s, y = vel[b + 1] * s, z = vel[b + 2] * s;
    d32[idx] = make_float4(x, y, z, 0.0f);
    d16[idx] = pack_h16(x, y, z);
}

// One squaring step: vout = v + trilinear_sample(v, identity + v).
// Own-voxel v in fp32; 8-corner gather from the fp16 mirror.
template <bool LAST>
__global__ void __launch_bounds__(256)
step_kernel(const float4* __restrict__ vin32,
            const uint2*  __restrict__ vin16,
            float4* __restrict__ vout32,
            uint2*  __restrict__ vout16,
            float*  __restrict__ vout_packed)
{
    int idx = blockIdx.x * blockDim.x + threadIdx.x;
    if (idx >= N_VOX) return;

    int ix = idx % DIM;
    int t  = idx / DIM;
    int iy = t % DIM;
    int iz = t / DIM;

    float4 v = __ldg(&vin32[idx]);

    const float half = 0.5f * (float)(DIM - 1);  // 79.5
    float x = (float)ix + half * v.x;
    float y = (float)iy + half * v.y;
    float z = (float)iz + half * v.z;

    float xf = floorf(x), yf = floorf(y), zf = floorf(z);
    int x0 = (int)xf, y0 = (int)yf, z0 = (int)zf;
    float fx = x - xf, fy = y - yf, fz = z - zf;
    float wx0 = 1.0f - fx, wx1 = fx;
    float wy[2] = {1.0f - fy, fy};
    float wz[2] = {1.0f - fz, fz};

    float ax = 0.0f, ay = 0.0f, az = 0.0f;

    bool lo_ok = ((unsigned)x0 < (unsigned)DIM);
    bool hi_ok = ((unsigned)(x0 + 1) < (unsigned)DIM);
    bool pair  = ((x0 & 1) == 0) && lo_ok && hi_ok;

#pragma unroll
    for (int c = 0; c < 4; c++) {
        int dy = c & 1, dz = c >> 1;
        int yy = y0 + dy, zz = z0 + dz;
        if (((unsigned)yy < (unsigned)DIM) & ((unsigned)zz < (unsigned)DIM)) {
            float wyz = wy[dy] * wz[dz];
            int rb = (zz * DIM + yy) * DIM;
            if (pair) {
                // one LDG.128 fetches BOTH x-corners (x0 even, 16B aligned)
                uint4 p = __ldg(reinterpret_cast<const uint4*>(vin16 + rb + x0));
                float2 lxy = __half22float2(*reinterpret_cast<__half2*>(&p.x));
                float2 lz_ = __half22float2(*reinterpret_cast<__half2*>(&p.y));
                float2 hxy = __half22float2(*reinterpret_cast<__half2*>(&p.z));
                float2 hz_ = __half22float2(*reinterpret_cast<__half2*>(&p.w));
                float wl = wyz * wx0, wh = wyz * wx1;
                ax = fmaf(wl, lxy.x, fmaf(wh, hxy.x, ax));
                ay = fmaf(wl, lxy.y, fmaf(wh, hxy.y, ay));
                az = fmaf(wl, lz_.x, fmaf(wh, hz_.x, az));
            } else {
                if (lo_ok) {
                    uint2 q = __ldg(vin16 + rb + x0);
                    float2 xy = __half22float2(*reinterpret_cast<__half2*>(&q.x));
                    float2 z_ = __half22float2(*reinterpret_cast<__half2*>(&q.y));
                    float w = wyz * wx0;
                    ax = fmaf(w, xy.x, ax);
                    ay = fmaf(w, xy.y, ay);
                    az = fmaf(w, z_.x, az);
                }
                if (hi_ok) {
                    uint2 q = __ldg(vin16 + rb + x0 + 1);
                    float2 xy = __half22float2(*reinterpret_cast<__half2*>(&q.x));
                    float2 z_ = __half22float2(*reinterpret_cast<__half2*>(&q.y));
                    float w = wyz * wx1;
                    ax = fmaf(w, xy.x, ax);
                    ay = fmaf(w, xy.y, ay);
                    az = fmaf(w, z_.x, az);
                }
            }
        }
    }

    float ox = v.x + ax, oy = v.y + ay, oz = v.z + az;

    if (LAST) {
        int b = idx * 3;
        vout_packed[b + 0] = ox;
        vout_packed[b + 1] = oy;
        vout_packed[b + 2] = oz;
    } else {
        vout32[idx] = make_float4(ox, oy, oz, 0.0f);
        vout16[idx] = pack_h16(ox, oy, oz);
    }
}

extern "C" void kernel_launch(void* const* d_in, const int* in_sizes, int n_in,
                              void* d_out, int out_size)
{
    const float* vel = (const float*)d_in[0];  // [1,160,160,160,3] f32
    // d_in[1] = grid (analytic identity; recomputed from index). d_in[2] = n (= 6).
    float* out = (float*)d_out;

    float4 *f32A, *f32B;
    uint2  *h16A, *h16B;
    cudaGetSymbolAddress((void**)&f32A, g_f32A);
    cudaGetSymbolAddress((void**)&f32B, g_f32B);
    cudaGetSymbolAddress((void**)&h16A, g_h16A);
    cudaGetSymbolAddress((void**)&h16B, g_h16B);

    const int threads = 256;
    const int blocks = (N_VOX + threads - 1) / threads;

    repack_kernel<<<blocks, threads>>>(vel, f32A, h16A, 1.0f / 64.0f);

    step_kernel<false><<<blocks, threads>>>(f32A, h16A, f32B, h16B, nullptr);
    step_kernel<false><<<blocks, threads>>>(f32B, h16B, f32A, h16A, nullptr);
    step_kernel<false><<<blocks, threads>>>(f32A, h16A, f32B, h16B, nullptr);
    step_kernel<false><<<blocks, threads>>>(f32B, h16B, f32A, h16A, nullptr);
    step_kernel<false><<<blocks, threads>>>(f32A, h16A, f32B, h16B, nullptr);
    step_kernel<true ><<<blocks, threads>>>(f32B, h16B, nullptr, nullptr, out);
}

// round 4
// speedup vs baseline: 1.2949x; 1.2949x over previous
#include <cuda_runtime.h>
#include <cuda_fp16.h>

#define DIM 160
#define N_VOX (DIM * DIM * DIM)

// fp32 carried field (ping-pong) — own-voxel read (coordinates + additive term)
__device__ float4 g_f32A[N_VOX];
__device__ float4 g_f32B[N_VOX];
// fp16x4 mirror (8B/voxel) — gather source only.
__device__ __align__(16) uint2 g_h16A[N_VOX];
__device__ __align__(16) uint2 g_h16B[N_VOX];

__device__ __forceinline__ uint2 pack_h16(float x, float y, float z)
{
    __half2 hxy = __floats2half2_rn(x, y);
    __half2 hz  = __floats2half2_rn(z, 0.0f);
    uint2 r;
    r.x = *reinterpret_cast<unsigned int*>(&hxy);
    r.y = *reinterpret_cast<unsigned int*>(&hz);
    return r;
}

__device__ __forceinline__ void unpack_h16(uint2 q, float& x, float& y, float& z)
{
    float2 xy = __half22float2(*reinterpret_cast<__half2*>(&q.x));
    float2 z_ = __half22float2(*reinterpret_cast<__half2*>(&q.y));
    x = xy.x; y = xy.y; z = z_.x;
}

// Repack + prescale: vel (packed 12B voxels) -> fp32 + fp16 buffers, scaled 2^-n.
__global__ void __launch_bounds__(256)
repack_kernel(const float4* __restrict__ vel4,
              float4* __restrict__ d32, uint2* __restrict__ d16, float s)
{
    int t = blockIdx.x * blockDim.x + threadIdx.x;   // one thread = 4 voxels
    if (t >= N_VOX / 4) return;
    float4 a = vel4[3 * t + 0];
    float4 b = vel4[3 * t + 1];
    float4 c = vel4[3 * t + 2];
    int i = 4 * t;
    d32[i + 0] = make_float4(a.x * s, a.y * s, a.z * s, 0.0f);
    d32[i + 1] = make_float4(a.w * s, b.x * s, b.y * s, 0.0f);
    d32[i + 2] = make_float4(b.z * s, b.w * s, c.x * s, 0.0f);
    d32[i + 3] = make_float4(c.y * s, c.z * s, c.w * s, 0.0f);
    d16[i + 0] = pack_h16(a.x * s, a.y * s, a.z * s);
    d16[i + 1] = pack_h16(a.w * s, b.x * s, b.y * s);
    d16[i + 2] = pack_h16(b.z * s, b.w * s, c.x * s);
    d16[i + 3] = pack_h16(c.y * s, c.z * s, c.w * s);
}

// One squaring step: vout = v + trilinear_sample(v, identity + v).
// Own-voxel v in fp32; 8-corner gather from the fp16 mirror. Branch-free:
// out-of-range axes are clamped and their weight zeroed.
template <bool LAST>
__global__ void __launch_bounds__(160)
step_kernel(const float4* __restrict__ vin32,
            const uint2*  __restrict__ vin16,
            float4* __restrict__ vout32,
            uint2*  __restrict__ vout16,
            float*  __restrict__ vout_packed)
{
    int ix = threadIdx.x;
    int iy = blockIdx.x;
    int iz = blockIdx.y;
    int idx = (iz * DIM + iy) * DIM + ix;

    float4 v = __ldg(&vin32[idx]);

    const float half = 0.5f * (float)(DIM - 1);  // 79.5
    float x = (float)ix + half * v.x;
    float y = (float)iy + half * v.y;
    float z = (float)iz + half * v.z;

    float xf = floorf(x), yf = floorf(y), zf = floorf(z);
    int x0 = (int)xf, y0 = (int)yf, z0 = (int)zf;
    float fx = x - xf, fy = y - yf, fz = z - zf;

    // Clamped indices + masked weights (branch-free bounds handling)
    int x0c = min(max(x0, 0), DIM - 1);
    int x1c = min(max(x0 + 1, 0), DIM - 1);
    int y0c = min(max(y0, 0), DIM - 1);
    int y1c = min(max(y0 + 1, 0), DIM - 1);
    int z0c = min(max(z0, 0), DIM - 1);
    int z1c = min(max(z0 + 1, 0), DIM - 1);
    float wx0 = ((unsigned)x0       < (unsigned)DIM) ? (1.0f - fx) : 0.0f;
    float wx1 = ((unsigned)(x0 + 1) < (unsigned)DIM) ? fx          : 0.0f;
    float wy0 = ((unsigned)y0       < (unsigned)DIM) ? (1.0f - fy) : 0.0f;
    float wy1 = ((unsigned)(y0 + 1) < (unsigned)DIM) ? fy          : 0.0f;
    float wz0 = ((unsigned)z0       < (unsigned)DIM) ? (1.0f - fz) : 0.0f;
    float wz1 = ((unsigned)(z0 + 1) < (unsigned)DIM) ? fz          : 0.0f;

    int rb00 = (z0c * DIM + y0c) * DIM;
    int rb01 = (z0c * DIM + y1c) * DIM;
    int rb10 = (z1c * DIM + y0c) * DIM;
    int rb11 = (z1c * DIM + y1c) * DIM;
    float w00 = wz0 * wy0, w01 = wz0 * wy1, w10 = wz1 * wy0, w11 = wz1 * wy1;

    float ax = 0.0f, ay = 0.0f, az = 0.0f;

#pragma unroll
    for (int c = 0; c < 8; c++) {
        int rb;
        float wyz;
        switch (c >> 1) {
            case 0: rb = rb00; wyz = w00; break;
            case 1: rb = rb01; wyz = w01; break;
            case 2: rb = rb10; wyz = w10; break;
            default: rb = rb11; wyz = w11; break;
        }
        int xi   = (c & 1) ? x1c : x0c;
        float w  = wyz * ((c & 1) ? wx1 : wx0);
        uint2 q = __ldg(vin16 + rb + xi);
        float cx, cy, cz;
        unpack_h16(q, cx, cy, cz);
        ax = fmaf(w, cx, ax);
        ay = fmaf(w, cy, ay);
        az = fmaf(w, cz, az);
    }

    float ox = v.x + ax, oy = v.y + ay, oz = v.z + az;

    if (LAST) {
        int b = idx * 3;
        vout_packed[b + 0] = ox;
        vout_packed[b + 1] = oy;
        vout_packed[b + 2] = oz;
    } else {
        vout32[idx] = make_float4(ox, oy, oz, 0.0f);
        vout16[idx] = pack_h16(ox, oy, oz);
    }
}

extern "C" void kernel_launch(void* const* d_in, const int* in_sizes, int n_in,
                              void* d_out, int out_size)
{
    const float* vel = (const float*)d_in[0];  // [1,160,160,160,3] f32
    // d_in[1] = grid (analytic identity; recomputed from index). d_in[2] = n (= 6).
    float* out = (float*)d_out;

    float4 *f32A, *f32B;
    uint2  *h16A, *h16B;
    cudaGetSymbolAddress((void**)&f32A, g_f32A);
    cudaGetSymbolAddress((void**)&f32B, g_f32B);
    cudaGetSymbolAddress((void**)&h16A, g_h16A);
    cudaGetSymbolAddress((void**)&h16B, g_h16B);

    {
        int n4 = N_VOX / 4;
        repack_kernel<<<(n4 + 255) / 256, 256>>>(
            (const float4*)vel, f32A, h16A, 1.0f / 64.0f);
    }

    dim3 grid(DIM, DIM);
    dim3 block(DIM);
    step_kernel<false><<<grid, block>>>(f32A, h16A, f32B, h16B, nullptr);
    step_kernel<false><<<grid, block>>>(f32B, h16B, f32A, h16A, nullptr);
    step_kernel<false><<<grid, block>>>(f32A, h16A, f32B, h16B, nullptr);
    step_kernel<false><<<grid, block>>>(f32B, h16B, f32A, h16A, nullptr);
    step_kernel<false><<<grid, block>>>(f32A, h16A, f32B, h16B, nullptr);
    step_kernel<true ><<<grid, block>>>(f32B, h16B, nullptr, nullptr, out);
}